// round 11
// baseline (speedup 1.0000x reference)
#include <cuda_runtime.h>
#include <cuda_fp16.h>
#include <cstdint>

// Problem shape (fixed): B=32, Q=512, K=512, D=1024, fp32.
// Inputs: queries f32[B,Q,D], keys f32[B,K,D], temperature f32[], bias f32[]
// Output: attn f32[B,Q,K] then confidence f32[B,Q].
//
// GEMM via 2-product fp16 "Karatsuba" split on mma.sync (HMMA):
//   h = fp16(x), l = x-h, v = fp16(h + 128*l)
//   P1 = h.h', P2 = v.v'   ->   x.x' ~= P1 + (P2-P1)/128   (err ~1e-4 abs)
// This is 2/3 the MMA-instruction count of the 3-product bf16 scheme, and
// mma.sync instruction rate (16 cyc/SMSP) is the measured bottleneck.

#define BATCH 32
#define QDIM 512
#define KDIM 512
#define DDIM 1024

#define TM 128
#define TN 128
#define CK 16                    // k floats per stage
#define NST (DDIM / CK)          // 64 stages
#define LAMBDA 128.0f
#define INV_LAMBDA (1.0f / 128.0f)

// ---------------- PTX helpers ----------------
__device__ __forceinline__ uint32_t smem_u32(const void* p) {
    uint32_t a;
    asm("{ .reg .u64 t; cvta.to.shared.u64 t, %1; cvt.u32.u64 %0, t; }"
        : "=r"(a) : "l"(p));
    return a;
}

#define LDSM4(r0, r1, r2, r3, addr)                                        \
    asm volatile("ldmatrix.sync.aligned.m8n8.x4.shared.b16 "               \
                 "{%0, %1, %2, %3}, [%4];"                                 \
                 : "=r"(r0), "=r"(r1), "=r"(r2), "=r"(r3) : "r"(addr))

#define STS128(addr, r0, r1, r2, r3)                                       \
    asm volatile("st.shared.v4.b32 [%0], {%1, %2, %3, %4};"                \
                 :: "r"(addr), "r"(r0), "r"(r1), "r"(r2), "r"(r3) : "memory")

#define MMAF16(c, a0, a1, a2, a3, b0, b1)                                  \
    asm volatile("mma.sync.aligned.m16n8k16.row.col.f32.f16.f16.f32 "      \
                 "{%0, %1, %2, %3}, {%4, %5, %6, %7}, {%8, %9}, "          \
                 "{%0, %1, %2, %3};"                                       \
                 : "+f"((c)[0]), "+f"((c)[1]), "+f"((c)[2]), "+f"((c)[3])  \
                 : "r"(a0), "r"(a1), "r"(a2), "r"(a3), "r"(b0), "r"(b1))

// h = fp16(x); v = fp16(h + 128*(x-h)); packed as half2 pairs.
__device__ __forceinline__ void cvt2(float x, float y,
                                     uint32_t& h, uint32_t& v) {
    __half hx = __float2half_rn(x), hy = __float2half_rn(y);
    float fx = __half2float(hx),    fy = __half2float(hy);
    float vx = fmaf(LAMBDA, x - fx, fx);
    float vy = fmaf(LAMBDA, y - fy, fy);
    __half2 hh = __halves2half2(hx, hy);
    __half2 vv = __floats2half2_rn(vx, vy);
    h = *reinterpret_cast<uint32_t*>(&hh);
    v = *reinterpret_cast<uint32_t*>(&vv);
}

// Swizzled byte offset: row r (0..127), 16-byte chunk c (0..1), 32B rows.
__device__ __forceinline__ uint32_t swz(int r, int c) {
    return (uint32_t)(r * 32 + ((c ^ ((r >> 2) & 1)) << 4));
}

// ---------------------------------------------------------------------------
// GEMM: logits = Q*K^T, 2-product fp16 split; key mask -> -inf.
// CTA 128x128, 512 threads, warps 4(M) x 4(N), warp tile 32x32.
// Double-buffered smem, one barrier per stage.
// ---------------------------------------------------------------------------
__global__ __launch_bounds__(512, 1)
void gemm_f16k_kernel(const float* __restrict__ Qg,
                      const float* __restrict__ Kg,
                      float* __restrict__ Cg) {
    __shared__ __align__(128) uint8_t sAh[2][4096], sAv[2][4096];
    __shared__ __align__(128) uint8_t sBh[2][4096], sBv[2][4096];
    __shared__ float maskv[TN];

    const int tid  = threadIdx.x;
    const int lane = tid & 31;
    const int wid  = tid >> 5;         // 0..15
    const int wm   = wid & 3;          // M
    const int wn   = wid >> 2;         // N

    const int bn = blockIdx.x * TN;
    const int bm = blockIdx.y * TM;
    const int b  = blockIdx.z;

    const float* A  = Qg + (size_t)b * QDIM * DDIM;
    const float* Bp = Kg + (size_t)b * KDIM * DDIM;
    float*       C  = Cg + (size_t)b * QDIM * KDIM;

    if (tid < TN)
        maskv[tid] = (Bp[(size_t)(bn + tid) * DDIM] == 0.0f) ? 1.0f : 0.0f;

    // ---- producer mapping: threads 0-255 -> A, 256-511 -> B ----
    const int slot = tid & 255;
    const int pr = slot >> 1;          // row 0..127
    const int ph = slot & 1;           // 16B k-chunk
    const bool isA = (tid < 256);
    const uint32_t so = swz(pr, ph);
    const uint32_t stH = (isA ? smem_u32(sAh) : smem_u32(sBh)) + so;
    const uint32_t stV = (isA ? smem_u32(sAv) : smem_u32(sBv)) + so;
    const float* gsrc = (isA ? A + (size_t)(bm + pr) * DDIM
                             : Bp + (size_t)(bn + pr) * DDIM) + ph * 8;

    // ---- ldmatrix addresses (buffer 0; +4096 selects buffer 1) ----
    uint32_t lmA, lmB;
    {
        int r = wm * 32 + (lane & 15);
        int c = lane >> 4;
        lmA = swz(r, c);
    }
    {
        int r = wn * 32 + (lane & 7) + ((lane >> 4) << 3);
        int c = (lane >> 3) & 1;
        lmB = swz(r, c);
    }
    const uint32_t aAh = smem_u32(sAh) + lmA;
    const uint32_t aAv = smem_u32(sAv) + lmA;
    const uint32_t aBh = smem_u32(sBh) + lmB;
    const uint32_t aBv = smem_u32(sBv) + lmB;

    float acc1[2][4][4], acc2[2][4][4];
    #pragma unroll
    for (int i = 0; i < 2; ++i)
        #pragma unroll
        for (int j = 0; j < 4; ++j)
            #pragma unroll
            for (int k = 0; k < 4; ++k) { acc1[i][j][k] = 0.0f; acc2[i][j][k] = 0.0f; }

    // ---- prologue: stage 0 -> buf0; prefetch stage 1 ----
    float4 v0 = *(const float4*)gsrc;
    float4 v1 = *(const float4*)(gsrc + 4);
    {
        uint32_t h0, h1, h2, h3, w0, w1, w2, w3;
        cvt2(v0.x, v0.y, h0, w0); cvt2(v0.z, v0.w, h1, w1);
        cvt2(v1.x, v1.y, h2, w2); cvt2(v1.z, v1.w, h3, w3);
        STS128(stH, h0, h1, h2, h3);
        STS128(stV, w0, w1, w2, w3);
    }
    gsrc += CK;
    v0 = *(const float4*)gsrc;
    v1 = *(const float4*)(gsrc + 4);
    __syncthreads();

    for (int s = 0; s < NST; ++s) {
        const uint32_t rd = (uint32_t)(s & 1) * 4096;
        const uint32_t wr = 4096 - rd;

        // ---- A fragments from the read buffer ----
        uint32_t Ah[2][4], Av[2][4];
        LDSM4(Ah[0][0], Ah[0][1], Ah[0][2], Ah[0][3], aAh + rd);
        LDSM4(Ah[1][0], Ah[1][1], Ah[1][2], Ah[1][3], aAh + rd + 512);
        LDSM4(Av[0][0], Av[0][1], Av[0][2], Av[0][3], aAv + rd);
        LDSM4(Av[1][0], Av[1][1], Av[1][2], Av[1][3], aAv + rd + 512);

        // ---- split + store NEXT stage into the write buffer ----
        if (s + 1 < NST) {
            uint32_t h0, h1, h2, h3, w0, w1, w2, w3;
            cvt2(v0.x, v0.y, h0, w0); cvt2(v0.z, v0.w, h1, w1);
            cvt2(v1.x, v1.y, h2, w2); cvt2(v1.z, v1.w, h3, w3);
            STS128(stH + wr, h0, h1, h2, h3);
            STS128(stV + wr, w0, w1, w2, w3);
        }
        // ---- prefetch stage s+2 from gmem ----
        if (s + 2 < NST) {
            gsrc += CK;
            v0 = *(const float4*)gsrc;
            v1 = *(const float4*)(gsrc + 4);
        }

        // ---- 4 B-LDSM + 16 HMMA ----
        #pragma unroll
        for (int p = 0; p < 2; ++p) {          // 16 n-cols per iter
            uint32_t Bh[4], Bv[4];
            LDSM4(Bh[0], Bh[1], Bh[2], Bh[3], aBh + rd + p * 512);
            LDSM4(Bv[0], Bv[1], Bv[2], Bv[3], aBv + rd + p * 512);
            #pragma unroll
            for (int mi = 0; mi < 2; ++mi) {
                MMAF16(acc1[mi][2 * p],     Ah[mi][0], Ah[mi][1], Ah[mi][2], Ah[mi][3], Bh[0], Bh[1]);
                MMAF16(acc1[mi][2 * p + 1], Ah[mi][0], Ah[mi][1], Ah[mi][2], Ah[mi][3], Bh[2], Bh[3]);
                MMAF16(acc2[mi][2 * p],     Av[mi][0], Av[mi][1], Av[mi][2], Av[mi][3], Bv[0], Bv[1]);
                MMAF16(acc2[mi][2 * p + 1], Av[mi][0], Av[mi][1], Av[mi][2], Av[mi][3], Bv[2], Bv[3]);
            }
        }
        __syncthreads();
    }

    // ---- epilogue: combine P1 + (P2-P1)/lambda, mask, store ----
    const float NEG_INF = __int_as_float(0xff800000);
    const int mrow = bm + wm * 32 + (lane >> 2);
    const int ncl  = wn * 32 + (lane & 3) * 2;
    #pragma unroll
    for (int mi = 0; mi < 2; ++mi) {
        #pragma unroll
        for (int nj = 0; nj < 4; ++nj) {
            const int nc = ncl + nj * 8;
            const float m0 = maskv[nc];
            const float m1 = maskv[nc + 1];
            const float* p1 = acc1[mi][nj];
            const float* p2 = acc2[mi][nj];
            float r0 = fmaf(p2[0] - p1[0], INV_LAMBDA, p1[0]);
            float r1 = fmaf(p2[1] - p1[1], INV_LAMBDA, p1[1]);
            float r2 = fmaf(p2[2] - p1[2], INV_LAMBDA, p1[2]);
            float r3 = fmaf(p2[3] - p1[3], INV_LAMBDA, p1[3]);
            float2 o0, o1;
            o0.x = (m0 != 0.0f) ? NEG_INF : r0;
            o0.y = (m1 != 0.0f) ? NEG_INF : r1;
            o1.x = (m0 != 0.0f) ? NEG_INF : r2;
            o1.y = (m1 != 0.0f) ? NEG_INF : r3;
            float* base = C + (size_t)(mrow + mi * 16) * KDIM + bn + nc;
            *(float2*)base              = o0;
            *(float2*)(base + 8 * KDIM) = o1;
        }
    }
}

// ---------------------------------------------------------------------------
// Softmax + confidence
// ---------------------------------------------------------------------------
__global__ __launch_bounds__(128)
void softmax_conf_kernel(const float* __restrict__ tptr,
                         const float* __restrict__ bptr,
                         float* __restrict__ out) {
    __shared__ float red[4];
    const int row = blockIdx.x;
    float* lr = out + (size_t)row * KDIM;
    const int tid = threadIdx.x;

    float4 v = *(const float4*)(lr + tid * 4);

    float m = fmaxf(fmaxf(v.x, v.y), fmaxf(v.z, v.w));
    #pragma unroll
    for (int o = 16; o > 0; o >>= 1)
        m = fmaxf(m, __shfl_xor_sync(0xffffffffu, m, o));
    if ((tid & 31) == 0) red[tid >> 5] = m;
    __syncthreads();
    m = fmaxf(fmaxf(red[0], red[1]), fmaxf(red[2], red[3]));
    __syncthreads();

    float e0 = __expf(v.x - m);
    float e1 = __expf(v.y - m);
    float e2 = __expf(v.z - m);
    float e3 = __expf(v.w - m);
    float s = (e0 + e1) + (e2 + e3);
    #pragma unroll
    for (int o = 16; o > 0; o >>= 1)
        s += __shfl_xor_sync(0xffffffffu, s, o);
    if ((tid & 31) == 0) red[tid >> 5] = s;
    __syncthreads();
    s = (red[0] + red[1]) + (red[2] + red[3]);

    const float inv = 1.0f / s;
    *(float4*)(lr + tid * 4) = make_float4(e0 * inv, e1 * inv, e2 * inv, e3 * inv);

    if (tid == 0) {
        const float lse = m + logf(s);
        const float x = (lse + bptr[0]) * tptr[0];
        out[(size_t)BATCH * QDIM * KDIM + row] = 1.0f / (1.0f + __expf(-x));
    }
}

// ---------------------------------------------------------------------------
extern "C" void kernel_launch(void* const* d_in, const int* in_sizes, int n_in,
                              void* d_out, int out_size) {
    const float* q    = (const float*)d_in[0];
    const float* k    = (const float*)d_in[1];
    const float* temp = (const float*)d_in[2];
    const float* bias = (const float*)d_in[3];
    float* out = (float*)d_out;

    dim3 ggrid(KDIM / TN, QDIM / TM, BATCH);   // (4, 4, 32)
    gemm_f16k_kernel<<<ggrid, 512>>>(q, k, out);

    softmax_conf_kernel<<<BATCH * QDIM, 128>>>(temp, bias, out);
}